// round 6
// baseline (speedup 1.0000x reference)
#include <cuda_runtime.h>
#include <cstdint>

// Problem constants
#define NB    16
#define CD    256
#define HH    80
#define WW    60
#define LL    4800            // HH*WW
#define NHD   8
#define HDD   32
#define MR    (NB*LL)         // 76800 rows

#define EPI_NONE     0
#define EPI_ELU1     1
#define EPI_RELU_RND 2

// ---------------- scratch (static device globals; no allocation) ----------------
__device__ float g_F0 [(size_t)MR * CD];   // exact x (residual/output)
__device__ float g_F0r[(size_t)MR * CD];   // tf32-rounded shadow of F0 (GEMM A)
__device__ float g_F1 [(size_t)MR * CD];   // tf32-rounded (GEMM-only consumer)
__device__ float g_Q  [(size_t)MR * CD];
__device__ float g_K  [(size_t)MR * CD];
__device__ float g_V  [(size_t)MR * CD];
__device__ float g_PE [(size_t)CD * LL];
__device__ float g_KV [NB * NHD * HDD * HDD];
__device__ float g_KS [NB * NHD * HDD];
// tf32-rounded weights (original [K][N] layout)
__device__ float g_Wq[2 * CD * CD];
__device__ float g_Wk[2 * CD * CD];
__device__ float g_Wv[2 * CD * CD];
__device__ float g_Wm[2 * CD * CD];
__device__ float g_W1[2 * 2 * CD * CD];
__device__ float g_W2[2 * CD * CD];

__device__ __forceinline__ float rnd_tf32(float x) {
    float r;
    asm("cvt.rna.tf32.f32 %0, %1;" : "=f"(r) : "f"(x));
    return r;
}

// ---------------- weight prep: round all weights to tf32 once ----------------
__global__ void weight_prep_kernel(
    const float* __restrict__ wq, const float* __restrict__ wk,
    const float* __restrict__ wv, const float* __restrict__ wm,
    const float* __restrict__ w1, const float* __restrict__ w2)
{
    int i = blockIdx.x * blockDim.x + threadIdx.x;
    const int S = 2 * CD * CD;
    if (i < S) g_Wq[i] = rnd_tf32(wq[i]);
    if (i < S) g_Wk[i] = rnd_tf32(wk[i]);
    if (i < S) g_Wv[i] = rnd_tf32(wv[i]);
    if (i < S) g_Wm[i] = rnd_tf32(wm[i]);
    if (i < S) g_W2[i] = rnd_tf32(w2[i]);
    if (i < 2 * S) g_W1[i] = rnd_tf32(w1[i]);
}

// ---------------- positional encoding ----------------
// fac = (-log(1e4)/256)//2 == -1.0  =>  div[j] = exp(-2*j)
__global__ void pe_precompute_kernel(float* __restrict__ PE) {
    int idx = blockIdx.x * blockDim.x + threadIdx.x;
    if (idx >= CD * LL) return;
    int c = idx / LL, l = idx % LL;
    int j = c >> 2, r = c & 3;
    int h = l / WW, w = l % WW;
    float f = expf(-2.0f * (float)j);
    float pos = (r < 2) ? (float)(w + 1) : (float)(h + 1);
    float arg = pos * f;
    PE[idx] = (r & 1) ? cosf(arg) : sinf(arg);
}

__global__ void build_pe_kernel(const float* __restrict__ feat, const float* __restrict__ PE,
                                float* __restrict__ out, float* __restrict__ outR) {
    __shared__ float tile[32][33];
    int n  = blockIdx.z;
    int c0 = blockIdx.y * 32;
    int l0 = blockIdx.x * 32;
    int tx = threadIdx.x, ty = threadIdx.y;
#pragma unroll
    for (int i = 0; i < 4; i++) {
        int c = c0 + ty + i * 8;
        int l = l0 + tx;
        tile[ty + i * 8][tx] = feat[((size_t)n * CD + c) * LL + l] + PE[(size_t)c * LL + l];
    }
    __syncthreads();
#pragma unroll
    for (int i = 0; i < 4; i++) {
        int l = l0 + ty + i * 8;
        int c = c0 + tx;
        float v = tile[tx][ty + i * 8];
        size_t o = ((size_t)n * LL + l) * CD + c;
        if (out)  out[o]  = v;
        if (outR) outR[o] = rnd_tf32(v);
    }
}

__global__ void unbuild_kernel(const float* __restrict__ in, float* __restrict__ out) {
    __shared__ float tile[32][33];
    int n  = blockIdx.z;
    int c0 = blockIdx.y * 32;
    int l0 = blockIdx.x * 32;
    int tx = threadIdx.x, ty = threadIdx.y;
#pragma unroll
    for (int i = 0; i < 4; i++) {
        int l = l0 + ty + i * 8;
        int c = c0 + tx;
        tile[ty + i * 8][tx] = in[((size_t)n * LL + l) * CD + c];
    }
    __syncthreads();
#pragma unroll
    for (int i = 0; i < 4; i++) {
        int c = c0 + ty + i * 8;
        int l = l0 + tx;
        out[((size_t)n * CD + c) * LL + l] = tile[tx][ty + i * 8];
    }
}

// ---------------- TF32 tensor-core GEMM, fragment-packed SMEM ----------------
// C[M,256] = epi( [A|A2][M,Ktot] @ B[Ktot,256] ), row-major, inputs pre-rounded.
// BM=128, BN=128 (grid.x=2), BK=16, 8 warps, warp tile 32x64 (m16n8k8).
// As2 layout (words): [ks(2)][blk16(8)][g(8)][q(4)][reg(4)]  => A frag = 1 LDS.128
//   value at [ks][b][g][q][reg]: reg = dq*2+hi -> A[b*16 + hi*8 + g][ks*8 + dq*4 + q]
// Bs2 layout (words): [k(16) stride 132][half(2)*64][nt(8)*8][g(8)] => 2 LDS.128 per k-row
//   value: B[k][half*64 + nt*8 + g]
#define BSTRIDE 132

__global__ __launch_bounds__(256, 2) void tgemm_kernel(
    const float* __restrict__ A, const float* __restrict__ A2,
    const float* __restrict__ B, float* __restrict__ C,
    int M, int Ktot, int K1, int N, int epi)
{
    __shared__ float As2[2][2048];
    __shared__ float Bs2[2][16 * BSTRIDE];

    int tid = threadIdx.x;
    int warp = tid >> 5;
    int lane = tid & 31;
    int g = lane >> 2;
    int qq = lane & 3;
    int rowBase = blockIdx.y * 128;
    int colBase = blockIdx.x * 128;
    int b16base = (warp >> 1) * 2;   // warp covers blk16 {b16base, b16base+1}
    int half = warp & 1;             // warp N half (64 cols)
    int K2 = Ktot - K1;
    int NS = Ktot >> 4;

    float acc[2][8][4];
#pragma unroll
    for (int mt = 0; mt < 2; mt++)
#pragma unroll
        for (int nt = 0; nt < 8; nt++)
#pragma unroll
            for (int r = 0; r < 4; r++) acc[mt][nt][r] = 0.0f;

    // ---- fill mappings ----
    // A chunks: c = tid (rows 0..63), tid+256 (rows 64..127); row=c>>2, kq=c&3
    int aRow = tid >> 2, aKq = tid & 3;
    int aKs = aKq >> 1, aDq = aKq & 1;
    // word index in As2 for [ks][blk16][g][q][reg]: ks*1024 + b*128 + g*16 + q*4 + reg
    // this thread stores A[row][ks*8 + dq*4 + q] for q=0..3 -> reg = dq*2 + hi,
    // where hi = (row>>3)&1, b = row>>4, g = row&7.
    int aBase0 = aKs * 1024 + (aRow >> 4) * 128 + (aRow & 7) * 16 + (aDq * 2 + ((aRow >> 3) & 1));
    int aBase1 = aBase0 + 4 * 128;   // row+64: blk16 += 4
    // B chunks: c = tid (k 0..7), tid+256 (k 8..15); k=c>>5, nq=c&31
    int bK = tid >> 5, bNq = tid & 31;

    uint4 rA0, rA1, rB0, rB1;

    auto ldg = [&](int s) {
        int k0 = s << 4;
        int kk = k0 + aKq * 4;
        const float* srcA0 = (kk < K1) ? (A  + (size_t)(rowBase + aRow) * K1 + kk)
                                       : (A2 + (size_t)(rowBase + aRow) * K2 + (kk - K1));
        const float* srcA1 = (kk < K1) ? (A  + (size_t)(rowBase + aRow + 64) * K1 + kk)
                                       : (A2 + (size_t)(rowBase + aRow + 64) * K2 + (kk - K1));
        rA0 = *(const uint4*)srcA0;
        rA1 = *(const uint4*)srcA1;
        rB0 = *(const uint4*)(B + (size_t)(k0 + bK) * N + colBase + bNq * 4);
        rB1 = *(const uint4*)(B + (size_t)(k0 + bK + 8) * N + colBase + bNq * 4);
    };

    auto sts = [&](int buf) {
        float* Ad = As2[buf];
        float* Bd = Bs2[buf];
        // A: q varies across the 4 loaded words; stride 4 words apart
        Ad[aBase0 +  0] = __uint_as_float(rA0.x);
        Ad[aBase0 +  4] = __uint_as_float(rA0.y);
        Ad[aBase0 +  8] = __uint_as_float(rA0.z);
        Ad[aBase0 + 12] = __uint_as_float(rA0.w);
        Ad[aBase1 +  0] = __uint_as_float(rA1.x);
        Ad[aBase1 +  4] = __uint_as_float(rA1.y);
        Ad[aBase1 +  8] = __uint_as_float(rA1.z);
        Ad[aBase1 + 12] = __uint_as_float(rA1.w);
        uint32_t bv0[4] = {rB0.x, rB0.y, rB0.z, rB0.w};
        uint32_t bv1[4] = {rB1.x, rB1.y, rB1.z, rB1.w};
#pragma unroll
        for (int j = 0; j < 4; j++) {
            int n = bNq * 4 + j;
            // word: half*64 + nt*8 + g  with nt=(n>>3)&7, g=n&7... but fragment wants
            // consecutive nt at consecutive addresses for LDS.128 across nt? No:
            // frag loads {nt0..nt7} for fixed g. Use layout: half*64 + g*8 + nt.
            int w = (n >> 6) * 64 + (n & 7) * 8 + ((n >> 3) & 7);
            Bd[bK * BSTRIDE + w]       = __uint_as_float(bv0[j]);
            Bd[(bK + 8) * BSTRIDE + w] = __uint_as_float(bv1[j]);
        }
    };

    ldg(0);
    sts(0);
    __syncthreads();

    for (int s = 0; s < NS; s++) {
        int bs = s & 1;
        if (s + 1 < NS) ldg(s + 1);

        const float* AsB = As2[bs];
        const float* BsB = Bs2[bs];
#pragma unroll
        for (int ks = 0; ks < 2; ks++) {
            uint4 av0 = *(const uint4*)(AsB + ks * 1024 + b16base * 128 + g * 16 + qq * 4);
            uint4 av1 = *(const uint4*)(AsB + ks * 1024 + (b16base + 1) * 128 + g * 16 + qq * 4);
            int r0 = ks * 8 + qq;
            const float* bp = BsB + half * 64 + g * 8;
            uint4 bl0 = *(const uint4*)(bp + r0 * BSTRIDE);
            uint4 bh0 = *(const uint4*)(bp + r0 * BSTRIDE + 4);
            uint4 bl1 = *(const uint4*)(bp + (r0 + 4) * BSTRIDE);
            uint4 bh1 = *(const uint4*)(bp + (r0 + 4) * BSTRIDE + 4);
            uint32_t af[2][4] = {{av0.x, av0.y, av0.z, av0.w},
                                 {av1.x, av1.y, av1.z, av1.w}};
            uint32_t b0[8] = {bl0.x, bl0.y, bl0.z, bl0.w, bh0.x, bh0.y, bh0.z, bh0.w};
            uint32_t b1[8] = {bl1.x, bl1.y, bl1.z, bl1.w, bh1.x, bh1.y, bh1.z, bh1.w};
#pragma unroll
            for (int mt = 0; mt < 2; mt++)
#pragma unroll
                for (int nt = 0; nt < 8; nt++) {
                    asm volatile(
                        "mma.sync.aligned.m16n8k8.row.col.f32.tf32.tf32.f32 "
                        "{%0,%1,%2,%3}, {%4,%5,%6,%7}, {%8,%9}, {%0,%1,%2,%3};\n"
                        : "+f"(acc[mt][nt][0]), "+f"(acc[mt][nt][1]),
                          "+f"(acc[mt][nt][2]), "+f"(acc[mt][nt][3])
                        : "r"(af[mt][0]), "r"(af[mt][1]), "r"(af[mt][2]), "r"(af[mt][3]),
                          "r"(b0[nt]), "r"(b1[nt]));
                }
        }
        if (s + 1 < NS) sts(bs ^ 1);
        __syncthreads();
    }

    // epilogue: c0,c1 -> (row g, col 2q), c2,c3 -> (row g+8, col 2q)
    int wm0 = (warp >> 1) * 32;
    int wn0 = half * 64;
#pragma unroll
    for (int mt = 0; mt < 2; mt++) {
        int row = rowBase + wm0 + mt * 16 + g;
#pragma unroll
        for (int nt = 0; nt < 8; nt++) {
            int col = colBase + wn0 + nt * 8 + 2 * qq;
            float v0 = acc[mt][nt][0], v1 = acc[mt][nt][1];
            float v2 = acc[mt][nt][2], v3 = acc[mt][nt][3];
            if (epi == EPI_ELU1) {
                v0 = (v0 > 0.f) ? v0 + 1.f : expf(v0);
                v1 = (v1 > 0.f) ? v1 + 1.f : expf(v1);
                v2 = (v2 > 0.f) ? v2 + 1.f : expf(v2);
                v3 = (v3 > 0.f) ? v3 + 1.f : expf(v3);
            } else if (epi == EPI_RELU_RND) {
                v0 = rnd_tf32(fmaxf(v0, 0.f)); v1 = rnd_tf32(fmaxf(v1, 0.f));
                v2 = rnd_tf32(fmaxf(v2, 0.f)); v3 = rnd_tf32(fmaxf(v3, 0.f));
            }
            *(float2*)(C + (size_t)row * N + col)       = make_float2(v0, v1);
            *(float2*)(C + (size_t)(row + 8) * N + col) = make_float2(v2, v3);
        }
    }
}

// ---------------- KV = sum_s K[s,d] * v[s,e], Ksum per (n,h) ----------------
#define KV_CHUNKS 20
#define KV_SC (LL / KV_CHUNKS)
__global__ void kv_reduce_kernel(const float* __restrict__ Kb, const float* __restrict__ Vb,
                                 float* __restrict__ KV, float* __restrict__ KS) {
    int nh = blockIdx.x;
    int n = nh >> 3, h = nh & 7;
    int t = threadIdx.x;
    int d = t & 31;
    int eg = t >> 5;
    int s0 = blockIdx.y * KV_SC;
    float a0 = 0, a1 = 0, a2 = 0, a3 = 0, ks = 0;
    for (int s = s0; s < s0 + KV_SC; s++) {
        size_t base = ((size_t)(n * LL + s) * NHD + h) * HDD;
        float kd = Kb[base + d];
        float4 vv = *(const float4*)(Vb + base + eg * 4);
        a0 = fmaf(kd, vv.x, a0);
        a1 = fmaf(kd, vv.y, a1);
        a2 = fmaf(kd, vv.z, a2);
        a3 = fmaf(kd, vv.w, a3);
        ks += kd;
    }
    float* kvp = KV + ((size_t)nh * HDD + d) * HDD + eg * 4;
    atomicAdd(kvp + 0, a0);
    atomicAdd(kvp + 1, a1);
    atomicAdd(kvp + 2, a2);
    atomicAdd(kvp + 3, a3);
    if (eg == 0) atomicAdd(KS + nh * HDD + d, ks);
}

// ---------------- out[n,l,h,e] = (Q.KV[:,e]) / (Q.Ksum + eps), tf32-rounded ----------------
#define AT_CHUNKS 40
#define AT_RPB (LL / AT_CHUNKS)
__global__ void attn_apply_kernel(const float* __restrict__ Qb, const float* __restrict__ KV,
                                  const float* __restrict__ KS, float* __restrict__ O) {
    __shared__ float kvs[32][33];
    __shared__ float kss[32];
    int n = blockIdx.z, h = blockIdx.y;
    int nh = n * NHD + h;
    int t = threadIdx.x, lane = t & 31, w = t >> 5;
    for (int i = t; i < 1024; i += 256) kvs[i >> 5][i & 31] = KV[(size_t)nh * 1024 + i];
    if (t < 32) kss[t] = KS[nh * 32 + t];
    __syncthreads();
    int l0 = blockIdx.x * AT_RPB + w * (AT_RPB / 8);
    for (int r = 0; r < AT_RPB / 8; r++) {
        int l = l0 + r;
        size_t base = ((size_t)(n * LL + l) * NHD + h) * HDD;
        float qd = Qb[base + lane];
        float zs = qd * kss[lane];
#pragma unroll
        for (int o = 16; o; o >>= 1) zs += __shfl_xor_sync(0xffffffffu, zs, o);
        float z = 1.0f / (zs + 1e-6f);
        float acc = 0.0f;
#pragma unroll
        for (int d = 0; d < 32; d++) {
            float qv = __shfl_sync(0xffffffffu, qd, d);
            acc = fmaf(qv, kvs[d][lane], acc);
        }
        O[base + lane] = rnd_tf32(acc * z);
    }
}

// ---------------- LayerNorm over 256, output tf32-rounded (feeds GEMM) ----------------
__global__ void layernorm_kernel(float* __restrict__ X,
                                 const float* __restrict__ g, const float* __restrict__ b) {
    int row = blockIdx.x * 8 + (threadIdx.x >> 5);
    int lane = threadIdx.x & 31;
    size_t base = (size_t)row * CD;
    float v[8];
    float s = 0.0f;
#pragma unroll
    for (int i = 0; i < 8; i++) { v[i] = X[base + i * 32 + lane]; s += v[i]; }
#pragma unroll
    for (int o = 16; o; o >>= 1) s += __shfl_xor_sync(0xffffffffu, s, o);
    float mu = s * (1.0f / 256.0f);
    float q = 0.0f;
#pragma unroll
    for (int i = 0; i < 8; i++) { float d = v[i] - mu; q = fmaf(d, d, q); }
#pragma unroll
    for (int o = 16; o; o >>= 1) q += __shfl_xor_sync(0xffffffffu, q, o);
    float rs = rsqrtf(q * (1.0f / 256.0f) + 1e-5f);
#pragma unroll
    for (int i = 0; i < 8; i++)
        X[base + i * 32 + lane] =
            rnd_tf32((v[i] - mu) * rs * g[i * 32 + lane] + b[i * 32 + lane]);
}

// X += LayerNorm(Y); Xr = tf32(X)
__global__ void ln_residual_kernel(float* __restrict__ X, float* __restrict__ Xr,
                                   const float* __restrict__ Y,
                                   const float* __restrict__ g, const float* __restrict__ b) {
    int row = blockIdx.x * 8 + (threadIdx.x >> 5);
    int lane = threadIdx.x & 31;
    size_t base = (size_t)row * CD;
    float v[8];
    float s = 0.0f;
#pragma unroll
    for (int i = 0; i < 8; i++) { v[i] = Y[base + i * 32 + lane]; s += v[i]; }
#pragma unroll
    for (int o = 16; o; o >>= 1) s += __shfl_xor_sync(0xffffffffu, s, o);
    float mu = s * (1.0f / 256.0f);
    float q = 0.0f;
#pragma unroll
    for (int i = 0; i < 8; i++) { float d = v[i] - mu; q = fmaf(d, d, q); }
#pragma unroll
    for (int o = 16; o; o >>= 1) q += __shfl_xor_sync(0xffffffffu, q, o);
    float rs = rsqrtf(q * (1.0f / 256.0f) + 1e-5f);
#pragma unroll
    for (int i = 0; i < 8; i++) {
        size_t o = base + i * 32 + lane;
        float nx = X[o] + (v[i] - mu) * rs * g[i * 32 + lane] + b[i * 32 + lane];
        X[o] = nx;
        Xr[o] = rnd_tf32(nx);
    }
}

// ---------------- launch ----------------
extern "C" void kernel_launch(void* const* d_in, const int* in_sizes, int n_in,
                              void* d_out, int out_size) {
    const float* feat0 = (const float*)d_in[0];
    const float* feat1 = (const float*)d_in[1];
    const float* Wq = (const float*)d_in[2];
    const float* Wk = (const float*)d_in[3];
    const float* Wv = (const float*)d_in[4];
    const float* Wm = (const float*)d_in[5];
    const float* W1 = (const float*)d_in[6];
    const float* W2 = (const float*)d_in[7];
    const float* g1 = (const float*)d_in[8];
    const float* b1 = (const float*)d_in[9];
    const float* g2 = (const float*)d_in[10];
    const float* b2 = (const float*)d_in[11];

    float *F0, *F0r, *F1, *Qb, *Kb, *Vb, *KV, *KS, *PE;
    float *wQ, *wK, *wV, *wM, *w1p, *w2p;
    cudaGetSymbolAddress((void**)&F0,  g_F0);
    cudaGetSymbolAddress((void**)&F0r, g_F0r);
    cudaGetSymbolAddress((void**)&F1,  g_F1);
    cudaGetSymbolAddress((void**)&Qb,  g_Q);
    cudaGetSymbolAddress((void**)&Kb,  g_K);
    cudaGetSymbolAddress((void**)&Vb,  g_V);
    cudaGetSymbolAddress((void**)&KV,  g_KV);
    cudaGetSymbolAddress((void**)&KS,  g_KS);
    cudaGetSymbolAddress((void**)&PE,  g_PE);
    cudaGetSymbolAddress((void**)&wQ,  g_Wq);
    cudaGetSymbolAddress((void**)&wK,  g_Wk);
    cudaGetSymbolAddress((void**)&wV,  g_Wv);
    cudaGetSymbolAddress((void**)&wM,  g_Wm);
    cudaGetSymbolAddress((void**)&w1p, g_W1);
    cudaGetSymbolAddress((void**)&w2p, g_W2);

    weight_prep_kernel<<<(2 * 2 * CD * CD + 255) / 256, 256>>>(Wq, Wk, Wv, Wm, W1, W2);
    pe_precompute_kernel<<<(CD * LL + 255) / 256, 256>>>(PE);

    dim3 tb(32, 8);
    dim3 tg(LL / 32, CD / 32, NB);
    build_pe_kernel<<<tg, tb>>>(feat0, PE, F0, F0r);
    build_pe_kernel<<<tg, tb>>>(feat1, PE, nullptr, F1);

    dim3 gg(CD / 128, MR / 128);

    for (int i = 0; i < 2; i++) {
        const float* wq = wQ + (size_t)i * CD * CD;
        const float* wk = wK + (size_t)i * CD * CD;
        const float* wv = wV + (size_t)i * CD * CD;
        const float* wm = wM + (size_t)i * CD * CD;
        const float* w1 = w1p + (size_t)i * 2 * CD * CD;
        const float* w2 = w2p + (size_t)i * CD * CD;

        tgemm_kernel<<<gg, 256>>>(F0r, F0r, wq, Qb, MR, CD, CD, CD, EPI_ELU1);
        tgemm_kernel<<<gg, 256>>>(F1,  F1,  wk, Kb, MR, CD, CD, CD, EPI_ELU1);
        tgemm_kernel<<<gg, 256>>>(F1,  F1,  wv, Vb, MR, CD, CD, CD, EPI_NONE);

        cudaMemsetAsync(KV, 0, sizeof(float) * NB * NHD * HDD * HDD, 0);
        cudaMemsetAsync(KS, 0, sizeof(float) * NB * NHD * HDD, 0);
        kv_reduce_kernel<<<dim3(NB * NHD, KV_CHUNKS), 256>>>(Kb, Vb, KV, KS);

        attn_apply_kernel<<<dim3(AT_CHUNKS, NHD, NB), 256>>>(Qb, KV, KS, Kb);

        tgemm_kernel<<<gg, 256>>>(Kb, Kb, wm, Vb, MR, CD, CD, CD, EPI_NONE);
        layernorm_kernel<<<MR / 8, 256>>>(Vb, g1 + i * CD, b1 + i * CD);

        tgemm_kernel<<<gg, 256>>>(F0r, Vb, w1, Qb, MR, 2 * CD, CD, CD, EPI_RELU_RND);
        tgemm_kernel<<<gg, 256>>>(Qb, Qb, w2, Kb, MR, CD, CD, CD, EPI_NONE);
        ln_residual_kernel<<<MR / 8, 256>>>(F0, F0r, Kb, g2 + i * CD, b2 + i * CD);
    }

    unbuild_kernel<<<tg, tb>>>(F0, (float*)d_out);
}